// round 10
// baseline (speedup 1.0000x reference)
#include <cuda_runtime.h>
#include <cuda_bf16.h>

// SymmetryConstraint — closed form per (batch, class) group (u = x - 0.5):
//   sum_{i<j}(u_i+u_j)^2 = (m-2)*sum(u^2) + (sum u)^2
//   sum_{i<j}(y_i-y_j)^2 = m*sum(y^2) - (sum y)^2
//   pairs = m*(m-1)/2
//
// R10: 32 blocks x 512 threads (8 batches/block, 2 warps/batch, 8 pts/lane).
// Only 32 same-address atomics total (L2 atomic drain ~27cyc/op serialized —
// this was ~1.5us of the R9 kernel at 128 blocks).
// Block publishes ONE fused u64 atomic:
//   bits[ 0:30) loss in 2^-7 fixed point   (total ~6.6e7 << 2^30)
//   bits[30:56) pair count                 (total ~1.55e6 << 2^26)
//   bits[56:64) arrival count
// Winner (arrivals==31) computes out[] from the atomic return value.
// Integer adds commute => bit-deterministic under any arrival order.

#define NPTS    512
#define NBATCH  256
#define TPB     512
#define BPB     8
#define NBLOCKS (NBATCH / BPB)   // 32

#define LOSS_BITS 30
#define CNT_SHIFT 30
#define ARR_SHIFT 56
#define LOSS_SCALE 128.0f

__device__ unsigned long long g_all = 0ull;

__global__ __launch_bounds__(TPB)
void symconstraint_kernel(const float* __restrict__ kp,   // [B, N, 2] f32
                          const int*   __restrict__ cls,  // [B, N]    i32
                          float*       __restrict__ out)  // [1]
{
    const int t    = threadIdx.x;
    const int warp = t >> 5;            // 0..15
    const int lane = t & 31;
    const int batch_local = warp >> 1;  // 0..7
    const int wib         = warp & 1;   // warp-in-batch
    const int batch       = blockIdx.x * BPB + batch_local;

    const float4* __restrict__ kp4  = reinterpret_cast<const float4*>(kp);
    const int2*   __restrict__ cls2 = reinterpret_cast<const int2*>(cls);

    // Batch row = 256 float4 (512 points); this warp covers half of it.
    const int base = batch * (NPTS / 2) + wib * 128 + lane;

    float4 q[4];
    int2   c2[4];
    #pragma unroll
    for (int i = 0; i < 4; i++) {
        q[i]  = kp4 [base + i * 32];
        c2[i] = cls2[base + i * 32];
    }

    float su[3]  = {0.f, 0.f, 0.f};
    float su2[3] = {0.f, 0.f, 0.f};
    float sy[3]  = {0.f, 0.f, 0.f};
    float sy2[3] = {0.f, 0.f, 0.f};
    int   cntp   = 0;   // 3 x 10-bit packed counts (max 256/warp/class)

    #pragma unroll
    for (int i = 0; i < 4; i++) {
        #pragma unroll
        for (int half = 0; half < 2; half++) {
            const int   c  = half ? c2[i].y : c2[i].x;
            const float xx = half ? q[i].z  : q[i].x;
            const float yy = half ? q[i].w  : q[i].y;
            const float u  = xx - 0.5f;
            const float uu = u * u;
            const float y2 = yy * yy;
            #pragma unroll
            for (int k = 0; k < 3; k++) {
                const bool h = (c == k);
                su[k]  += h ? u  : 0.f;
                su2[k] += h ? uu : 0.f;
                sy[k]  += h ? yy : 0.f;
                sy2[k] += h ? y2 : 0.f;
            }
            const unsigned uc = (unsigned)c;
            cntp += (uc <= 2u) ? (1 << (10u * (uc & 3u))) : 0;
        }
    }

    // Warp butterfly over 13 accumulators.
    #pragma unroll
    for (int o = 16; o > 0; o >>= 1) {
        #pragma unroll
        for (int k = 0; k < 3; k++) {
            su[k]  += __shfl_xor_sync(0xffffffffu, su[k],  o);
            su2[k] += __shfl_xor_sync(0xffffffffu, su2[k], o);
            sy[k]  += __shfl_xor_sync(0xffffffffu, sy[k],  o);
            sy2[k] += __shfl_xor_sync(0xffffffffu, sy2[k], o);
        }
        cntp += __shfl_xor_sync(0xffffffffu, cntp, o);
    }

    __shared__ float s_acc[16][12];
    __shared__ int   s_cnt[16];

    if (lane == 0) {
        #pragma unroll
        for (int k = 0; k < 3; k++) {
            s_acc[warp][k]     = su[k];
            s_acc[warp][3 + k] = su2[k];
            s_acc[warp][6 + k] = sy[k];
            s_acc[warp][9 + k] = sy2[k];
        }
        s_cnt[warp] = cntp;
    }
    __syncthreads();

    // Warp 0 finishes: lanes 0..7 each combine one batch's 2 warps, closed
    // form in fp32, fold lanes 0..7 via xor shuffles (closed group), lane 0
    // publishes the single fused atomic.
    if (warp == 0) {
        float loss = 0.f;
        int   pc   = 0;
        if (lane < BPB) {
            const int w0 = lane * 2;
            float a[12];
            #pragma unroll
            for (int j = 0; j < 12; j++)
                a[j] = s_acc[w0][j] + s_acc[w0 + 1][j];
            const int pk = s_cnt[w0] + s_cnt[w0 + 1];

            #pragma unroll
            for (int k = 0; k < 3; k++) {
                const int mi = (pk >> (10 * k)) & 1023;
                if (mi >= 2) {
                    const float m = (float)mi;
                    loss += (m - 2.f) * a[3 + k] + a[k] * a[k]
                          +  m        * a[9 + k] - a[6 + k] * a[6 + k];
                    pc   += (mi * (mi - 1)) >> 1;
                }
            }
        }
        #pragma unroll
        for (int o = 4; o > 0; o >>= 1) {
            loss += __shfl_xor_sync(0xffffffffu, loss, o);
            pc   += __shfl_xor_sync(0xffffffffu, pc,   o);
        }

        if (lane == 0) {
            const unsigned long long lfix =
                (unsigned long long)(loss * LOSS_SCALE + 0.5f);
            const unsigned long long mine =
                lfix
                + ((unsigned long long)pc << CNT_SHIFT)
                + (1ull << ARR_SHIFT);

            const unsigned long long ret = atomicAdd(&g_all, mine);

            if ((ret >> ARR_SHIFT) == NBLOCKS - 1) {          // we are last
                const unsigned long long tot = ret + mine;
                const float totL = (float)(tot & ((1ull << LOSS_BITS) - 1))
                                   * (1.0f / LOSS_SCALE);
                const float totC = (float)((tot >> CNT_SHIFT)
                                   & ((1ull << (ARR_SHIFT - CNT_SHIFT)) - 1));
                out[0] = totL / fmaxf(totC, 1.0f);
                atomicExch(&g_all, 0ull);   // replay-safe reset
            }
        }
    }
}

extern "C" void kernel_launch(void* const* d_in, const int* in_sizes, int n_in,
                              void* d_out, int out_size)
{
    const float* kp  = (const float*)d_in[0];
    const int*   cls = (const int*)d_in[1];
    float*       out = (float*)d_out;

    symconstraint_kernel<<<NBLOCKS, TPB>>>(kp, cls, out);
}